// round 4
// baseline (speedup 1.0000x reference)
#include <cuda_runtime.h>
#include <math.h>

// ---------------------------------------------------------------------------
// GCN 2-layer forward:  out = log_softmax( A' relu(A' (x W1) + b1) W2 + b2 )
// with A' = D^-1/2 (A + I) D^-1/2 built from edge_index.
//
// Strategy:
//   deg/dinv  : int histogram over dst, dinv = rsqrt(deg+1)
//   CSR       : counting sort of edges by dst (hist -> scan -> scatter)
//   layer     : hs = dinv[i] * (X W)   (scale fused in GEMM epilogue)
//               out_i = dinv[i] * ( hs_i + sum_{j->i} hs_j ) + b   (gather, NO atomics)
//   layer2    : GEMM first (128->64), aggregate 64-dim (half the traffic)
//   softmax   : fused into final aggregation warp (64 vals / warp)
// ---------------------------------------------------------------------------

#define NMAX 100000
#define EMAX 1600000
#define SCAN_BS 512
#define MAX_SCAN_BLOCKS 256   // ceil(100000/512)=196 <= 256

__device__ int g_cnt[NMAX];
__device__ int g_rowoff[NMAX + 1];
__device__ int g_cursor[NMAX];
__device__ int g_blksums[MAX_SCAN_BLOCKS];
__device__ int g_csr[EMAX];
__device__ float g_dinv[NMAX];
__device__ __align__(16) float g_hs1[(size_t)NMAX * 128];  // dinv * (x W1)
__device__ __align__(16) float g_h2[(size_t)NMAX * 128];   // relu(agg1)
__device__ __align__(16) float g_zs[(size_t)NMAX * 64];    // dinv * (h2 W2)

// ---------------------------------------------------------------------------
__global__ void k_zero_cnt(int n) {
    int i = blockIdx.x * blockDim.x + threadIdx.x;
    if (i < n) g_cnt[i] = 0;
}

__global__ void k_hist(const int* __restrict__ dst, int e) {
    int i = blockIdx.x * blockDim.x + threadIdx.x;
    if (i < e) atomicAdd(&g_cnt[dst[i]], 1);
}

__global__ void k_dinv(int n) {
    int i = blockIdx.x * blockDim.x + threadIdx.x;
    if (i < n) g_dinv[i] = rsqrtf((float)(g_cnt[i] + 1));  // +1 self loop
}

// exclusive scan of g_cnt -> g_rowoff, block partials to g_blksums
__global__ void k_scan1(int n) {
    __shared__ int s[SCAN_BS];
    int t = threadIdx.x;
    int i = blockIdx.x * SCAN_BS + t;
    int v = (i < n) ? g_cnt[i] : 0;
    s[t] = v;
    __syncthreads();
#pragma unroll
    for (int off = 1; off < SCAN_BS; off <<= 1) {
        int x = 0;
        if (t >= off) x = s[t - off];
        __syncthreads();
        s[t] += x;
        __syncthreads();
    }
    if (i < n) g_rowoff[i] = s[t] - v;  // exclusive within block
    if (t == SCAN_BS - 1) g_blksums[blockIdx.x] = s[t];
}

// exclusive scan of block sums (single block)
__global__ void k_scan2(int nb) {
    __shared__ int s[MAX_SCAN_BLOCKS];
    int t = threadIdx.x;
    int v = (t < nb) ? g_blksums[t] : 0;
    s[t] = v;
    __syncthreads();
#pragma unroll
    for (int off = 1; off < MAX_SCAN_BLOCKS; off <<= 1) {
        int x = 0;
        if (t >= off) x = s[t - off];
        __syncthreads();
        s[t] += x;
        __syncthreads();
    }
    if (t < nb) g_blksums[t] = s[t] - v;
}

__global__ void k_scan3(int n, int e) {
    int i = blockIdx.x * blockDim.x + threadIdx.x;
    if (i < n) {
        int r = g_rowoff[i] + g_blksums[i / SCAN_BS];
        g_rowoff[i] = r;
        g_cursor[i] = r;
    }
    if (i == 0) g_rowoff[n] = e;
}

__global__ void k_scatter(const int* __restrict__ src, const int* __restrict__ dst, int e) {
    int i = blockIdx.x * blockDim.x + threadIdx.x;
    if (i < e) {
        int d = dst[i];
        int p = atomicAdd(&g_cursor[d], 1);
        g_csr[p] = src[i];
    }
}

// ---------------------------------------------------------------------------
// GEMM: out[i][c] = dinv[i] * sum_k X[i][k] * W[k][c]     (K = 128 fixed)
// Block: 64 rows x NC cols, 256 threads, thread = 4 rows x NC/16 cols.
// ---------------------------------------------------------------------------
#define XS_STRIDE 129

template <int NC>
__global__ void k_gemm(const float* __restrict__ X, const float* __restrict__ W,
                       float* __restrict__ out, int n) {
    extern __shared__ float sm[];
    float* Ws = sm;                 // 128 * NC
    float* Xs = sm + 128 * NC;      // 64 * XS_STRIDE
    const int tid = threadIdx.x;
    const int row0 = blockIdx.x * 64;

    for (int i = tid; i < 128 * NC; i += 256) Ws[i] = W[i];
    for (int i = tid; i < 64 * 128; i += 256) {
        int r = i >> 7, c = i & 127;
        int gr = row0 + r;
        Xs[r * XS_STRIDE + c] = (gr < n) ? X[(size_t)gr * 128 + c] : 0.f;
    }
    __syncthreads();

    const int tr = tid >> 4;   // 0..15 -> rows tr*4 .. tr*4+3
    const int tc = tid & 15;   // cols tc + 16*j
    constexpr int TN = NC / 16;
    float acc[4][TN];
#pragma unroll
    for (int r = 0; r < 4; r++)
#pragma unroll
        for (int j = 0; j < TN; j++) acc[r][j] = 0.f;

#pragma unroll 2
    for (int k = 0; k < 128; k++) {
        float xr[4];
#pragma unroll
        for (int r = 0; r < 4; r++) xr[r] = Xs[(tr * 4 + r) * XS_STRIDE + k];
#pragma unroll
        for (int j = 0; j < TN; j++) {
            float w = Ws[k * NC + tc + 16 * j];
#pragma unroll
            for (int r = 0; r < 4; r++) acc[r][j] = fmaf(xr[r], w, acc[r][j]);
        }
    }

#pragma unroll
    for (int r = 0; r < 4; r++) {
        int gr = row0 + tr * 4 + r;
        if (gr < n) {
            float dv = g_dinv[gr];
#pragma unroll
            for (int j = 0; j < TN; j++)
                out[(size_t)gr * NC + tc + 16 * j] = dv * acc[r][j];
        }
    }
}

// ---------------------------------------------------------------------------
// Aggregation (gather form): one warp per node.
//   acc = hs[i] + sum_{j in CSR row i} hs[j]
//   out = act( dinv[i]*acc + b )
// NC=128: lane holds float4; NC=64: lane holds float2 (+fused log_softmax).
// ---------------------------------------------------------------------------
__global__ void k_agg_relu(const float* __restrict__ hs, const float* __restrict__ bias,
                           float* __restrict__ out, int n) {
    int gw = (blockIdx.x * blockDim.x + threadIdx.x) >> 5;
    int lane = threadIdx.x & 31;
    if (gw >= n) return;

    float4 acc = *(const float4*)(hs + (size_t)gw * 128 + lane * 4);  // self loop

    int p = g_rowoff[gw];
    int end = g_rowoff[gw + 1];
    for (; p + 3 < end; p += 4) {
        int j0 = g_csr[p], j1 = g_csr[p + 1], j2 = g_csr[p + 2], j3 = g_csr[p + 3];
        float4 v0 = *(const float4*)(hs + (size_t)j0 * 128 + lane * 4);
        float4 v1 = *(const float4*)(hs + (size_t)j1 * 128 + lane * 4);
        float4 v2 = *(const float4*)(hs + (size_t)j2 * 128 + lane * 4);
        float4 v3 = *(const float4*)(hs + (size_t)j3 * 128 + lane * 4);
        acc.x += v0.x + v1.x + v2.x + v3.x;
        acc.y += v0.y + v1.y + v2.y + v3.y;
        acc.z += v0.z + v1.z + v2.z + v3.z;
        acc.w += v0.w + v1.w + v2.w + v3.w;
    }
    for (; p < end; p++) {
        int j = g_csr[p];
        float4 v = *(const float4*)(hs + (size_t)j * 128 + lane * 4);
        acc.x += v.x; acc.y += v.y; acc.z += v.z; acc.w += v.w;
    }

    float dv = g_dinv[gw];
    float4 b = *(const float4*)(bias + lane * 4);
    float4 o;
    o.x = fmaxf(fmaf(dv, acc.x, b.x), 0.f);
    o.y = fmaxf(fmaf(dv, acc.y, b.y), 0.f);
    o.z = fmaxf(fmaf(dv, acc.z, b.z), 0.f);
    o.w = fmaxf(fmaf(dv, acc.w, b.w), 0.f);
    *(float4*)(out + (size_t)gw * 128 + lane * 4) = o;
}

__global__ void k_agg_softmax(const float* __restrict__ zs, const float* __restrict__ bias,
                              float* __restrict__ out, int n) {
    int gw = (blockIdx.x * blockDim.x + threadIdx.x) >> 5;
    int lane = threadIdx.x & 31;
    if (gw >= n) return;

    float2 acc = *(const float2*)(zs + (size_t)gw * 64 + lane * 2);  // self loop

    int p = g_rowoff[gw];
    int end = g_rowoff[gw + 1];
    for (; p + 3 < end; p += 4) {
        int j0 = g_csr[p], j1 = g_csr[p + 1], j2 = g_csr[p + 2], j3 = g_csr[p + 3];
        float2 v0 = *(const float2*)(zs + (size_t)j0 * 64 + lane * 2);
        float2 v1 = *(const float2*)(zs + (size_t)j1 * 64 + lane * 2);
        float2 v2 = *(const float2*)(zs + (size_t)j2 * 64 + lane * 2);
        float2 v3 = *(const float2*)(zs + (size_t)j3 * 64 + lane * 2);
        acc.x += v0.x + v1.x + v2.x + v3.x;
        acc.y += v0.y + v1.y + v2.y + v3.y;
    }
    for (; p < end; p++) {
        int j = g_csr[p];
        float2 v = *(const float2*)(zs + (size_t)j * 64 + lane * 2);
        acc.x += v.x; acc.y += v.y;
    }

    float dv = g_dinv[gw];
    float2 b = *(const float2*)(bias + lane * 2);
    float o0 = fmaf(dv, acc.x, b.x);
    float o1 = fmaf(dv, acc.y, b.y);

    // log_softmax over 64 values held 2-per-lane across the warp
    float m = fmaxf(o0, o1);
#pragma unroll
    for (int off = 16; off; off >>= 1) m = fmaxf(m, __shfl_xor_sync(0xffffffffu, m, off));
    float s = expf(o0 - m) + expf(o1 - m);
#pragma unroll
    for (int off = 16; off; off >>= 1) s += __shfl_xor_sync(0xffffffffu, s, off);
    float lse = m + logf(s);

    float2 o; o.x = o0 - lse; o.y = o1 - lse;
    *(float2*)(out + (size_t)gw * 64 + lane * 2) = o;
}

// ---------------------------------------------------------------------------
extern "C" void kernel_launch(void* const* d_in, const int* in_sizes, int n_in,
                              void* d_out, int out_size) {
    const float* x  = (const float*)d_in[0];
    const int*   ei = (const int*)d_in[1];
    const float* W1 = (const float*)d_in[2];
    const float* b1 = (const float*)d_in[3];
    const float* W2 = (const float*)d_in[4];
    const float* b2 = (const float*)d_in[5];
    float* out = (float*)d_out;

    const int n = in_sizes[0] / 128;   // nodes
    const int e = in_sizes[1] / 2;     // edges
    const int* src = ei;               // edge_index[0]
    const int* dst = ei + e;           // edge_index[1]

    const int TB = 256;
    const int gN = (n + TB - 1) / TB;
    const int gE = (e + TB - 1) / TB;
    const int nb = (n + SCAN_BS - 1) / SCAN_BS;

    // dynamic smem opt-in (>48KB) for the GEMM kernels
    const int SM1 = (128 * 128 + 64 * XS_STRIDE) * 4;
    const int SM2 = (128 * 64 + 64 * XS_STRIDE) * 4;
    cudaFuncSetAttribute(k_gemm<128>, cudaFuncAttributeMaxDynamicSharedMemorySize, SM1);
    cudaFuncSetAttribute(k_gemm<64>,  cudaFuncAttributeMaxDynamicSharedMemorySize, SM2);

    // ---- degree / dinv / CSR build ----
    k_zero_cnt<<<gN, TB>>>(n);
    k_hist<<<gE, TB>>>(dst, e);
    k_dinv<<<gN, TB>>>(n);
    k_scan1<<<nb, SCAN_BS>>>(n);
    k_scan2<<<1, MAX_SCAN_BLOCKS>>>(nb);
    k_scan3<<<gN, TB>>>(n, e);
    k_scatter<<<gE, TB>>>(src, dst, e);

    // ---- layer 1: hs1 = dinv * (x W1); h2 = relu(dinv*agg(hs1) + b1) ----
    int gG = (n + 63) / 64;
    k_gemm<128><<<gG, 256, SM1>>>(x, W1, g_hs1, n);
    int gA = (n * 32 + TB - 1) / TB;
    k_agg_relu<<<gA, TB>>>(g_hs1, b1, g_h2, n);

    // ---- layer 2: zs = dinv * (h2 W2); out = log_softmax(dinv*agg(zs) + b2) ----
    k_gemm<64><<<gG, 256, SM2>>>(g_h2, W2, g_zs, n);
    k_agg_softmax<<<gA, TB>>>(g_zs, b2, out, n);
}